// round 8
// baseline (speedup 1.0000x reference)
#include <cuda_runtime.h>
#include <cuda_bf16.h>
#include <cstdint>

#define N_NODES 100000
#define E_MAX   1600000
#define HID     128
#define NB_SCAN 128
#define GBM 128
#define CCH  16     // spmm cols per chunk
#define SSTR 18     // spmm smem row stride (floats, even)

typedef unsigned long long u64t;
typedef unsigned int u32t;

// ---------------- device scratch (no allocations allowed) ----------------
__device__ int   g_deg[N_NODES];
__device__ int   g_rowptr[N_NODES + 1];
__device__ int   g_fill[N_NODES];
__device__ int   g_bsum[NB_SCAN];
__device__ int   g_boff[NB_SCAN];
__device__ int   g_col[E_MAX];
__device__ float g_dinv[N_NODES];
__device__ float g_tx1[(size_t)N_NODES * HID];
__device__ float g_h1 [(size_t)N_NODES * HID];
__device__ float g_h2 [(size_t)N_NODES * HID];
__device__ float g_hg [64 * HID];
__device__ u32t  g_Wbhi[2 * HID * HID];
__device__ u32t  g_Wblo[2 * HID * HID];

// ---------------- helpers ----------------
__device__ __forceinline__ u32t pack_bf16(float lo_val, float hi_val) {
    u32t r;
    asm("cvt.rn.bf16x2.f32 %0, %1, %2;" : "=r"(r) : "f"(hi_val), "f"(lo_val));
    return r;
}
__device__ __forceinline__ void mma_bf16(float* c, const u32t* a, const u32t* b) {
    asm volatile("mma.sync.aligned.m16n8k16.row.col.f32.bf16.bf16.f32 "
        "{%0,%1,%2,%3}, {%4,%5,%6,%7}, {%8,%9}, {%0,%1,%2,%3};"
        : "+f"(c[0]), "+f"(c[1]), "+f"(c[2]), "+f"(c[3])
        : "r"(a[0]), "r"(a[1]), "r"(a[2]), "r"(a[3]), "r"(b[0]), "r"(b[1]));
}
__device__ __forceinline__ void fadd2(u64t &d, u64t a) {
    asm("add.rn.f32x2 %0, %0, %1;" : "+l"(d) : "l"(a));
}
__device__ __forceinline__ float2 unpack2(u64t v) {
    float2 f; asm("mov.b64 {%0, %1}, %2;" : "=f"(f.x), "=f"(f.y) : "l"(v)); return f;
}

// ---------------- prep ----------------
__global__ void k_zero_deg(int n) {
    int i = blockIdx.x * blockDim.x + threadIdx.x;
    if (i < n) g_deg[i] = 0;
}

__global__ void k_hist(const int* __restrict__ dst, int e) {
    int i = blockIdx.x * blockDim.x + threadIdx.x;
    if (i < e) atomicAdd(&g_deg[dst[i]], 1);
}

__global__ void k_scanA(int n) {
    __shared__ int s[1024];
    int tid = threadIdx.x;
    int i = blockIdx.x * 1024 + tid;
    int v = (i < n) ? g_deg[i] : 0;
    s[tid] = v;
    __syncthreads();
    for (int off = 1; off < 1024; off <<= 1) {
        int t = (tid >= off) ? s[tid - off] : 0;
        __syncthreads();
        s[tid] += t;
        __syncthreads();
    }
    if (i < n) g_rowptr[i] = s[tid] - v;
    if (tid == 1023) g_bsum[blockIdx.x] = s[1023];
}

__global__ void k_scanB(int nb) {
    __shared__ int s[NB_SCAN];
    int tid = threadIdx.x;
    int v = (tid < nb) ? g_bsum[tid] : 0;
    s[tid] = v;
    __syncthreads();
    for (int off = 1; off < NB_SCAN; off <<= 1) {
        int t = (tid >= off) ? s[tid - off] : 0;
        __syncthreads();
        s[tid] += t;
        __syncthreads();
    }
    s[tid] -= v;
    g_boff[tid] = s[tid];
}

__global__ void k_scanC(int n, int e) {
    int i = blockIdx.x * 1024 + threadIdx.x;
    if (i < n) {
        int rp = g_rowptr[i] + g_boff[i >> 10];
        g_rowptr[i] = rp;
        g_fill[i]   = rp;
        g_dinv[i]   = rsqrtf(fmaxf((float)g_deg[i], 1.0f));
        if (i == n - 1) g_rowptr[n] = e;
    }
}

__global__ void k_fill(const int* __restrict__ src, const int* __restrict__ dst, int e) {
    int i = blockIdx.x * blockDim.x + threadIdx.x;
    if (i < e) {
        int p = atomicAdd(&g_fill[dst[i]], 1);
        g_col[p] = src[i];
    }
}

// ---------------- W prep (bf16 hi/lo, transposed, packed) ----------------
__global__ void k_wprep(const float* __restrict__ W1, const float* __restrict__ W2) {
    int i = blockIdx.x * 256 + threadIdx.x;
    int l  = i >> 14;
    int r  = i & 16383;
    int nn = r >> 7;
    int k2 = r & 127;
    const float* Wl = l ? W2 : W1;
    float v0 = Wl[(size_t)(2 * k2) * HID + nn];
    float v1 = Wl[(size_t)(2 * k2 + 1) * HID + nn];
    __nv_bfloat16 h0 = __float2bfloat16_rn(v0);
    __nv_bfloat16 h1 = __float2bfloat16_rn(v1);
    float l0 = v0 - __bfloat162float(h0);
    float l1 = v1 - __bfloat162float(h1);
    int o = l * (HID * HID) + nn * 128 + k2;
    g_Wbhi[o] = pack_bf16(__bfloat162float(h0), __bfloat162float(h1));
    g_Wblo[o] = pack_bf16(l0, l1);
}

// ---------------- SpMM v1 (fallback, round-2 proven) ----------------
__global__ void k_spmm(int layer, const float* __restrict__ xin, int n) {
    const float* __restrict__ feat = (layer == 0) ? xin : g_h1;
    int row = blockIdx.x * 8 + (threadIdx.x >> 5);
    if (row >= n) return;
    int lane = threadIdx.x & 31;
    int e0 = g_rowptr[row];
    int e1 = g_rowptr[row + 1];
    float4 acc = make_float4(0.f, 0.f, 0.f, 0.f);
    for (int e = e0; e < e1; e++) {
        int s = g_col[e];
        float w = g_dinv[s];
        float4 v = *(const float4*)&feat[(size_t)s * HID + lane * 4];
        acc.x += w * v.x;
        acc.y += w * v.y;
        acc.z += w * v.z;
        acc.w += w * v.w;
    }
    float sc = -g_dinv[row];
    acc.x *= sc; acc.y *= sc; acc.z *= sc; acc.w *= sc;
    *(float4*)&g_tx1[(size_t)row * HID + lane * 4] = acc;
}

// ---------------- SpMM v2: graph-tiled smem gather ----------------
// grid (B, HID/CCH). Block = (graph g, col chunk ch).
// Phase 1: stage dinv-premultiplied feat[g][:, c0:c0+16] into smem.
// Phase 2: per dst, 8-thread group gathers from smem (2 cols/thread, f32x2 adds).
__global__ __launch_bounds__(256) void k_spmm2(int layer, const float* __restrict__ xin,
                                               int gsize) {
    extern __shared__ float sfeat[];
    const float* __restrict__ feat = (layer == 0) ? xin : g_h1;
    int g  = blockIdx.x;
    int c0 = blockIdx.y * CCH;
    int gbase = g * gsize;
    int tid = threadIdx.x;

    // phase 1: load 2000 x 16 floats, premultiply by dinv[src]
    for (int idx = tid; idx < gsize * (CCH / 4); idx += 256) {
        int r = idx >> 2;
        int q = idx & 3;
        float4 v = *(const float4*)&feat[(size_t)(gbase + r) * HID + c0 + q * 4];
        float w = g_dinv[gbase + r];
        float* sp = &sfeat[r * SSTR + q * 4];
        sp[0] = v.x * w; sp[1] = v.y * w; sp[2] = v.z * w; sp[3] = v.w * w;
    }
    __syncthreads();

    int lane = tid & 31;
    int lig  = lane & 7;       // lane in 8-thread group
    int grp  = tid >> 3;       // dst slot 0..31
    int gb   = lane & 24;      // group base lane in warp

    for (int d0 = 0; d0 < gsize; d0 += 32) {
        int dl = d0 + grp;
        int e0 = 0, e1 = 0;
        if (dl < gsize) {
            e0 = g_rowptr[gbase + dl];
            e1 = g_rowptr[gbase + dl + 1];
        }
        int deg = e1 - e0;
        int rounds = (deg + 7) >> 3;
        // warp-uniform round count (max over the warp's 4 groups)
        rounds = max(rounds, __shfl_xor_sync(0xffffffffu, rounds, 8));
        rounds = max(rounds, __shfl_xor_sync(0xffffffffu, rounds, 16));

        u64t acc = 0ull;
        for (int r = 0; r < rounds; r++) {
            int e = e0 + r * 8 + lig;
            int cv = (e < e1) ? g_col[e] : gbase;
#pragma unroll
            for (int jj = 0; jj < 8; jj++) {
                int s = __shfl_sync(0xffffffffu, cv, gb + jj);
                u64t f = *(const u64t*)&sfeat[(s - gbase) * SSTR + (lig << 1)];
                if (r * 8 + jj < deg) fadd2(acc, f);
            }
        }

        if (dl < gsize) {
            float sc = -g_dinv[gbase + dl];
            float2 a = unpack2(acc);
            float2 o = make_float2(a.x * sc, a.y * sc);
            *(float2*)&g_tx1[(size_t)(gbase + dl) * HID + c0 + (lig << 1)] = o;
        }
    }
}

// ---------------- tensor GEMM (round-7 proven): C = relu([Afeat|g_tx1]@W + b) ----------------
__global__ __launch_bounds__(256, 2) void k_gemm_tc(int layer,
                                                    const float* __restrict__ xin,
                                                    const float* __restrict__ bias,
                                                    int n) {
    const float* __restrict__ Afeat = (layer == 0) ? xin : g_h1;
    float* __restrict__ C = (layer == 0) ? g_h1 : g_h2;
    const u32t* __restrict__ Whi = &g_Wbhi[layer * (HID * HID)];
    const u32t* __restrict__ Wlo = &g_Wblo[layer * (HID * HID)];

    __shared__ u32t As_hi[2][GBM][8];
    __shared__ u32t As_lo[2][GBM][8];
    __shared__ u32t Ws_hi[2][HID][8];
    __shared__ u32t Ws_lo[2][HID][8];

    int tid  = threadIdx.x;
    int lane = tid & 31;
    int wid  = tid >> 5;
    int wm   = wid & 1;
    int wn   = wid >> 1;
    int lr   = lane >> 2;
    int lc   = lane & 3;
    int bm   = blockIdx.x * GBM;
    int swl  = lr & 6;
    int ca   = lc ^ swl;

    float acc[4][4][4];
#pragma unroll
    for (int mi = 0; mi < 4; mi++)
#pragma unroll
        for (int ni = 0; ni < 4; ni++)
#pragma unroll
            for (int q = 0; q < 4; q++) acc[mi][ni][q] = 0.f;

    int tr = tid >> 2;
    int tq = tid & 3;

    for (int kb = 0; kb < 8; kb++) {
        int kg = kb * 32;
        const float* __restrict__ A = (kg < HID) ? Afeat : g_tx1;
        int kcol = kg & (HID - 1);

#pragma unroll
        for (int h = 0; h < 2; h++) {
#pragma unroll
            for (int p = 0; p < 2; p++) {
                int rl = tr + p * 64;
                int sw = rl & 6;
                int cc = (tq * 2) ^ sw;
                int row = bm + rl;
                float4 v = make_float4(0.f, 0.f, 0.f, 0.f);
                if (row < n) v = *(const float4*)&A[(size_t)row * HID + kcol + h * 16 + tq * 4];
                __nv_bfloat16 bx = __float2bfloat16_rn(v.x);
                __nv_bfloat16 by = __float2bfloat16_rn(v.y);
                __nv_bfloat16 bz = __float2bfloat16_rn(v.z);
                __nv_bfloat16 bw = __float2bfloat16_rn(v.w);
                float fx = __bfloat162float(bx), fy = __bfloat162float(by);
                float fz = __bfloat162float(bz), fw = __bfloat162float(bw);
                uint2 hi = make_uint2(pack_bf16(fx, fy), pack_bf16(fz, fw));
                uint2 lo = make_uint2(pack_bf16(v.x - fx, v.y - fy),
                                      pack_bf16(v.z - fz, v.w - fw));
                *(uint2*)&As_hi[h][rl][cc] = hi;
                *(uint2*)&As_lo[h][rl][cc] = lo;
                int wo = rl * 128 + (kg + h * 16) / 2 + tq * 2;
                *(uint2*)&Ws_hi[h][rl][cc] = *(const uint2*)&Whi[wo];
                *(uint2*)&Ws_lo[h][rl][cc] = *(const uint2*)&Wlo[wo];
            }
        }
        __syncthreads();

#pragma unroll
        for (int h = 0; h < 2; h++) {
            u32t bh[4][2], bl[4][2];
#pragma unroll
            for (int ni = 0; ni < 4; ni++) {
                int n0 = wn * 32 + ni * 8 + lr;
                bh[ni][0] = Ws_hi[h][n0][ca];
                bh[ni][1] = Ws_hi[h][n0][ca ^ 4];
                bl[ni][0] = Ws_lo[h][n0][ca];
                bl[ni][1] = Ws_lo[h][n0][ca ^ 4];
            }
#pragma unroll
            for (int mi = 0; mi < 4; mi++) {
                int m0 = wm * 64 + mi * 16;
                u32t ah[4], al[4];
                ah[0] = As_hi[h][m0 + lr][ca];
                ah[1] = As_hi[h][m0 + lr + 8][ca];
                ah[2] = As_hi[h][m0 + lr][ca ^ 4];
                ah[3] = As_hi[h][m0 + lr + 8][ca ^ 4];
                al[0] = As_lo[h][m0 + lr][ca];
                al[1] = As_lo[h][m0 + lr + 8][ca];
                al[2] = As_lo[h][m0 + lr][ca ^ 4];
                al[3] = As_lo[h][m0 + lr + 8][ca ^ 4];
#pragma unroll
                for (int ni = 0; ni < 4; ni++) {
                    mma_bf16(acc[mi][ni], ah, bh[ni]);
                    mma_bf16(acc[mi][ni], ah, bl[ni]);
                    mma_bf16(acc[mi][ni], al, bh[ni]);
                }
            }
        }
        __syncthreads();
    }

#pragma unroll
    for (int mi = 0; mi < 4; mi++) {
        int r0 = bm + wm * 64 + mi * 16 + lr;
        int r1 = r0 + 8;
#pragma unroll
        for (int ni = 0; ni < 4; ni++) {
            int col = wn * 32 + ni * 8 + lc * 2;
            float2 bv = *(const float2*)&bias[col];
            if (r0 < n) {
                float2 o;
                o.x = fmaxf(acc[mi][ni][0] + bv.x, 0.f);
                o.y = fmaxf(acc[mi][ni][1] + bv.y, 0.f);
                *(float2*)&C[(size_t)r0 * HID + col] = o;
            }
            if (r1 < n) {
                float2 o;
                o.x = fmaxf(acc[mi][ni][2] + bv.x, 0.f);
                o.y = fmaxf(acc[mi][ni][3] + bv.y, 0.f);
                *(float2*)&C[(size_t)r1 * HID + col] = o;
            }
        }
    }
}

// ---------------- segment max ----------------
__global__ void k_segmax(int gsize) {
    __shared__ float sm[8][HID];
    int g = blockIdx.x;
    int warp = threadIdx.x >> 5;
    int lane = threadIdx.x & 31;
    float4 m = make_float4(0.f, 0.f, 0.f, 0.f);
    int r0 = g * gsize;
    for (int r = r0 + warp; r < r0 + gsize; r += 8) {
        float4 v = *(const float4*)&g_h2[(size_t)r * HID + lane * 4];
        m.x = fmaxf(m.x, v.x);
        m.y = fmaxf(m.y, v.y);
        m.z = fmaxf(m.z, v.z);
        m.w = fmaxf(m.w, v.w);
    }
    *(float4*)&sm[warp][lane * 4] = m;
    __syncthreads();
    if (threadIdx.x < HID) {
        int f = threadIdx.x;
        float mm = sm[0][f];
#pragma unroll
        for (int w = 1; w < 8; w++) mm = fmaxf(mm, sm[w][f]);
        g_hg[g * HID + f] = mm;
    }
}

// ---------------- classifier head ----------------
__global__ void k_final(const float* __restrict__ Wc, const float* __restrict__ bc,
                        float* __restrict__ out, int nb) {
    int t = blockIdx.x * blockDim.x + threadIdx.x;
    if (t >= nb * 10) return;
    int g = t / 10;
    int c = t % 10;
    float acc = bc[c];
#pragma unroll 8
    for (int k = 0; k < HID; k++) acc += g_hg[g * HID + k] * Wc[k * 10 + c];
    out[t] = acc;
}

// ---------------- launch ----------------
extern "C" void kernel_launch(void* const* d_in, const int* in_sizes, int n_in,
                              void* d_out, int out_size) {
    const float* x   = (const float*)d_in[0];
    const float* W1  = (const float*)d_in[1];
    const float* b1  = (const float*)d_in[2];
    const float* W2  = (const float*)d_in[3];
    const float* b2  = (const float*)d_in[4];
    const float* Wc  = (const float*)d_in[5];
    const float* bc  = (const float*)d_in[6];
    const int*   src = (const int*)d_in[7];
    const int*   dst = (const int*)d_in[8];
    float* out = (float*)d_out;

    int e = in_sizes[7];
    int n = in_sizes[9];
    int nb_graphs = out_size / 10;
    int gsize = n / nb_graphs;
    int nbscan = (n + 1023) / 1024;
    int nGemm = (n + GBM - 1) / GBM;

    int spmm_smem = gsize * SSTR * (int)sizeof(float);
    bool use_v2 = (gsize % 4 == 0) && (gsize * nb_graphs == n) && (spmm_smem <= 160000);
    if (use_v2) {
        cudaFuncSetAttribute(k_spmm2, cudaFuncAttributeMaxDynamicSharedMemorySize, spmm_smem);
    }

    k_zero_deg<<<(n + 511) / 512, 512>>>(n);
    k_hist<<<(e + 511) / 512, 512>>>(dst, e);
    k_wprep<<<128, 256>>>(W1, W2);
    k_scanA<<<nbscan, 1024>>>(n);
    k_scanB<<<1, NB_SCAN>>>(nbscan);
    k_scanC<<<nbscan, 1024>>>(n, e);
    k_fill<<<(e + 511) / 512, 512>>>(src, dst, e);

    dim3 spmm_grid(nb_graphs, HID / CCH);

    // layer 1
    if (use_v2) k_spmm2<<<spmm_grid, 256, spmm_smem>>>(0, x, gsize);
    else        k_spmm<<<(n + 7) / 8, 256>>>(0, x, n);
    k_gemm_tc<<<nGemm, 256>>>(0, x, b1, n);
    // layer 2
    if (use_v2) k_spmm2<<<spmm_grid, 256, spmm_smem>>>(1, x, gsize);
    else        k_spmm<<<(n + 7) / 8, 256>>>(1, x, n);
    k_gemm_tc<<<nGemm, 256>>>(1, x, b2, n);

    k_segmax<<<nb_graphs, 256>>>(gsize);
    k_final<<<1, 512>>>(Wc, bc, out, nb_graphs);
}

// round 9
// speedup vs baseline: 2.5852x; 2.5852x over previous
#include <cuda_runtime.h>
#include <cuda_bf16.h>
#include <cstdint>

#define N_NODES 100000
#define E_MAX   1600000
#define HID     128
#define NB_SCAN 128
#define GBM 128

typedef unsigned long long u64t;
typedef unsigned int u32t;

// ---------------- device scratch (no allocations allowed) ----------------
__device__ int   g_deg[N_NODES];
__device__ int   g_rowptr[N_NODES + 1];
__device__ int   g_fill[N_NODES];
__device__ int   g_bsum[NB_SCAN];
__device__ int   g_boff[NB_SCAN];
__device__ int   g_col[E_MAX];
__device__ float g_dinv[N_NODES];
__device__ float g_tx1[(size_t)N_NODES * HID];
__device__ float g_h1 [(size_t)N_NODES * HID];
__device__ float g_h2 [(size_t)N_NODES * HID];
__device__ float g_hg [64 * HID];
__device__ u32t  g_Wbhi[2 * HID * HID];
__device__ u32t  g_Wblo[2 * HID * HID];

// ---------------- helpers ----------------
__device__ __forceinline__ u32t pack_bf16(float lo_val, float hi_val) {
    u32t r;
    asm("cvt.rn.bf16x2.f32 %0, %1, %2;" : "=r"(r) : "f"(hi_val), "f"(lo_val));
    return r;
}
__device__ __forceinline__ void mma_bf16(float* c, const u32t* a, const u32t* b) {
    asm volatile("mma.sync.aligned.m16n8k16.row.col.f32.bf16.bf16.f32 "
        "{%0,%1,%2,%3}, {%4,%5,%6,%7}, {%8,%9}, {%0,%1,%2,%3};"
        : "+f"(c[0]), "+f"(c[1]), "+f"(c[2]), "+f"(c[3])
        : "r"(a[0]), "r"(a[1]), "r"(a[2]), "r"(a[3]), "r"(b[0]), "r"(b[1]));
}

// ---------------- prep ----------------
__global__ void k_zero_deg(int n) {
    int i = blockIdx.x * blockDim.x + threadIdx.x;
    if (i < n) g_deg[i] = 0;
}

__global__ void k_hist(const int* __restrict__ dst, int e) {
    int i = blockIdx.x * blockDim.x + threadIdx.x;
    if (i < e) atomicAdd(&g_deg[dst[i]], 1);
}

__global__ void k_scanA(int n) {
    __shared__ int s[1024];
    int tid = threadIdx.x;
    int i = blockIdx.x * 1024 + tid;
    int v = (i < n) ? g_deg[i] : 0;
    s[tid] = v;
    __syncthreads();
    for (int off = 1; off < 1024; off <<= 1) {
        int t = (tid >= off) ? s[tid - off] : 0;
        __syncthreads();
        s[tid] += t;
        __syncthreads();
    }
    if (i < n) g_rowptr[i] = s[tid] - v;
    if (tid == 1023) g_bsum[blockIdx.x] = s[1023];
}

__global__ void k_scanB(int nb) {
    __shared__ int s[NB_SCAN];
    int tid = threadIdx.x;
    int v = (tid < nb) ? g_bsum[tid] : 0;
    s[tid] = v;
    __syncthreads();
    for (int off = 1; off < NB_SCAN; off <<= 1) {
        int t = (tid >= off) ? s[tid - off] : 0;
        __syncthreads();
        s[tid] += t;
        __syncthreads();
    }
    s[tid] -= v;
    g_boff[tid] = s[tid];
}

__global__ void k_scanC(int n, int e) {
    int i = blockIdx.x * 1024 + threadIdx.x;
    if (i < n) {
        int rp = g_rowptr[i] + g_boff[i >> 10];
        g_rowptr[i] = rp;
        g_fill[i]   = rp;
        g_dinv[i]   = rsqrtf(fmaxf((float)g_deg[i], 1.0f));
        if (i == n - 1) g_rowptr[n] = e;
    }
}

__global__ void k_fill(const int* __restrict__ src, const int* __restrict__ dst, int e) {
    int i = blockIdx.x * blockDim.x + threadIdx.x;
    if (i < e) {
        int p = atomicAdd(&g_fill[dst[i]], 1);
        g_col[p] = src[i];
    }
}

// ---------------- W prep (bf16 hi/lo, transposed, packed) ----------------
__global__ void k_wprep(const float* __restrict__ W1, const float* __restrict__ W2) {
    int i = blockIdx.x * 256 + threadIdx.x;
    int l  = i >> 14;
    int r  = i & 16383;
    int nn = r >> 7;
    int k2 = r & 127;
    const float* Wl = l ? W2 : W1;
    float v0 = Wl[(size_t)(2 * k2) * HID + nn];
    float v1 = Wl[(size_t)(2 * k2 + 1) * HID + nn];
    __nv_bfloat16 h0 = __float2bfloat16_rn(v0);
    __nv_bfloat16 h1 = __float2bfloat16_rn(v1);
    float l0 = v0 - __bfloat162float(h0);
    float l1 = v1 - __bfloat162float(h1);
    int o = l * (HID * HID) + nn * 128 + k2;
    g_Wbhi[o] = pack_bf16(__bfloat162float(h0), __bfloat162float(h1));
    g_Wblo[o] = pack_bf16(l0, l1);
}

// ---------------- SpMM: unrolled x4, dual accumulators (MLP >= 4) ----------------
__global__ void k_spmm(int layer, const float* __restrict__ xin, int n) {
    const float* __restrict__ feat = (layer == 0) ? xin : g_h1;
    int row = blockIdx.x * 8 + (threadIdx.x >> 5);
    if (row >= n) return;
    int lane = threadIdx.x & 31;
    int e0 = g_rowptr[row];
    int e1 = g_rowptr[row + 1];
    float4 acc0 = make_float4(0.f, 0.f, 0.f, 0.f);
    float4 acc1 = make_float4(0.f, 0.f, 0.f, 0.f);
    int e = e0;
    for (; e + 4 <= e1; e += 4) {
        int s0 = g_col[e];
        int s1 = g_col[e + 1];
        int s2 = g_col[e + 2];
        int s3 = g_col[e + 3];
        float w0 = g_dinv[s0], w1 = g_dinv[s1], w2 = g_dinv[s2], w3 = g_dinv[s3];
        float4 v0 = *(const float4*)&feat[(size_t)s0 * HID + lane * 4];
        float4 v1 = *(const float4*)&feat[(size_t)s1 * HID + lane * 4];
        float4 v2 = *(const float4*)&feat[(size_t)s2 * HID + lane * 4];
        float4 v3 = *(const float4*)&feat[(size_t)s3 * HID + lane * 4];
        acc0.x += w0 * v0.x; acc0.y += w0 * v0.y; acc0.z += w0 * v0.z; acc0.w += w0 * v0.w;
        acc1.x += w1 * v1.x; acc1.y += w1 * v1.y; acc1.z += w1 * v1.z; acc1.w += w1 * v1.w;
        acc0.x += w2 * v2.x; acc0.y += w2 * v2.y; acc0.z += w2 * v2.z; acc0.w += w2 * v2.w;
        acc1.x += w3 * v3.x; acc1.y += w3 * v3.y; acc1.z += w3 * v3.z; acc1.w += w3 * v3.w;
    }
    for (; e < e1; e++) {
        int s = g_col[e];
        float w = g_dinv[s];
        float4 v = *(const float4*)&feat[(size_t)s * HID + lane * 4];
        acc0.x += w * v.x; acc0.y += w * v.y; acc0.z += w * v.z; acc0.w += w * v.w;
    }
    float sc = -g_dinv[row];
    float4 o;
    o.x = (acc0.x + acc1.x) * sc;
    o.y = (acc0.y + acc1.y) * sc;
    o.z = (acc0.z + acc1.z) * sc;
    o.w = (acc0.w + acc1.w) * sc;
    *(float4*)&g_tx1[(size_t)row * HID + lane * 4] = o;
}

// ---------------- tensor GEMM (round-7 proven): C = relu([Afeat|g_tx1]@W + b) ----------------
__global__ __launch_bounds__(256, 2) void k_gemm_tc(int layer,
                                                    const float* __restrict__ xin,
                                                    const float* __restrict__ bias,
                                                    int n) {
    const float* __restrict__ Afeat = (layer == 0) ? xin : g_h1;
    float* __restrict__ C = (layer == 0) ? g_h1 : g_h2;
    const u32t* __restrict__ Whi = &g_Wbhi[layer * (HID * HID)];
    const u32t* __restrict__ Wlo = &g_Wblo[layer * (HID * HID)];

    __shared__ u32t As_hi[2][GBM][8];
    __shared__ u32t As_lo[2][GBM][8];
    __shared__ u32t Ws_hi[2][HID][8];
    __shared__ u32t Ws_lo[2][HID][8];

    int tid  = threadIdx.x;
    int lane = tid & 31;
    int wid  = tid >> 5;
    int wm   = wid & 1;
    int wn   = wid >> 1;
    int lr   = lane >> 2;
    int lc   = lane & 3;
    int bm   = blockIdx.x * GBM;
    int swl  = lr & 6;
    int ca   = lc ^ swl;

    float acc[4][4][4];
#pragma unroll
    for (int mi = 0; mi < 4; mi++)
#pragma unroll
        for (int ni = 0; ni < 4; ni++)
#pragma unroll
            for (int q = 0; q < 4; q++) acc[mi][ni][q] = 0.f;

    int tr = tid >> 2;
    int tq = tid & 3;

    for (int kb = 0; kb < 8; kb++) {
        int kg = kb * 32;
        const float* __restrict__ A = (kg < HID) ? Afeat : g_tx1;
        int kcol = kg & (HID - 1);

#pragma unroll
        for (int h = 0; h < 2; h++) {
#pragma unroll
            for (int p = 0; p < 2; p++) {
                int rl = tr + p * 64;
                int sw = rl & 6;
                int cc = (tq * 2) ^ sw;
                int row = bm + rl;
                float4 v = make_float4(0.f, 0.f, 0.f, 0.f);
                if (row < n) v = *(const float4*)&A[(size_t)row * HID + kcol + h * 16 + tq * 4];
                __nv_bfloat16 bx = __float2bfloat16_rn(v.x);
                __nv_bfloat16 by = __float2bfloat16_rn(v.y);
                __nv_bfloat16 bz = __float2bfloat16_rn(v.z);
                __nv_bfloat16 bw = __float2bfloat16_rn(v.w);
                float fx = __bfloat162float(bx), fy = __bfloat162float(by);
                float fz = __bfloat162float(bz), fw = __bfloat162float(bw);
                uint2 hi = make_uint2(pack_bf16(fx, fy), pack_bf16(fz, fw));
                uint2 lo = make_uint2(pack_bf16(v.x - fx, v.y - fy),
                                      pack_bf16(v.z - fz, v.w - fw));
                *(uint2*)&As_hi[h][rl][cc] = hi;
                *(uint2*)&As_lo[h][rl][cc] = lo;
                int wo = rl * 128 + (kg + h * 16) / 2 + tq * 2;
                *(uint2*)&Ws_hi[h][rl][cc] = *(const uint2*)&Whi[wo];
                *(uint2*)&Ws_lo[h][rl][cc] = *(const uint2*)&Wlo[wo];
            }
        }
        __syncthreads();

#pragma unroll
        for (int h = 0; h < 2; h++) {
            u32t bh[4][2], bl[4][2];
#pragma unroll
            for (int ni = 0; ni < 4; ni++) {
                int n0 = wn * 32 + ni * 8 + lr;
                bh[ni][0] = Ws_hi[h][n0][ca];
                bh[ni][1] = Ws_hi[h][n0][ca ^ 4];
                bl[ni][0] = Ws_lo[h][n0][ca];
                bl[ni][1] = Ws_lo[h][n0][ca ^ 4];
            }
#pragma unroll
            for (int mi = 0; mi < 4; mi++) {
                int m0 = wm * 64 + mi * 16;
                u32t ah[4], al[4];
                ah[0] = As_hi[h][m0 + lr][ca];
                ah[1] = As_hi[h][m0 + lr + 8][ca];
                ah[2] = As_hi[h][m0 + lr][ca ^ 4];
                ah[3] = As_hi[h][m0 + lr + 8][ca ^ 4];
                al[0] = As_lo[h][m0 + lr][ca];
                al[1] = As_lo[h][m0 + lr + 8][ca];
                al[2] = As_lo[h][m0 + lr][ca ^ 4];
                al[3] = As_lo[h][m0 + lr + 8][ca ^ 4];
#pragma unroll
                for (int ni = 0; ni < 4; ni++) {
                    mma_bf16(acc[mi][ni], ah, bh[ni]);
                    mma_bf16(acc[mi][ni], ah, bl[ni]);
                    mma_bf16(acc[mi][ni], al, bh[ni]);
                }
            }
        }
        __syncthreads();
    }

#pragma unroll
    for (int mi = 0; mi < 4; mi++) {
        int r0 = bm + wm * 64 + mi * 16 + lr;
        int r1 = r0 + 8;
#pragma unroll
        for (int ni = 0; ni < 4; ni++) {
            int col = wn * 32 + ni * 8 + lc * 2;
            float2 bv = *(const float2*)&bias[col];
            if (r0 < n) {
                float2 o;
                o.x = fmaxf(acc[mi][ni][0] + bv.x, 0.f);
                o.y = fmaxf(acc[mi][ni][1] + bv.y, 0.f);
                *(float2*)&C[(size_t)r0 * HID + col] = o;
            }
            if (r1 < n) {
                float2 o;
                o.x = fmaxf(acc[mi][ni][2] + bv.x, 0.f);
                o.y = fmaxf(acc[mi][ni][3] + bv.y, 0.f);
                *(float2*)&C[(size_t)r1 * HID + col] = o;
            }
        }
    }
}

// ---------------- segment max ----------------
__global__ void k_segmax(int gsize) {
    __shared__ float sm[8][HID];
    int g = blockIdx.x;
    int warp = threadIdx.x >> 5;
    int lane = threadIdx.x & 31;
    float4 m = make_float4(0.f, 0.f, 0.f, 0.f);
    int r0 = g * gsize;
    for (int r = r0 + warp; r < r0 + gsize; r += 8) {
        float4 v = *(const float4*)&g_h2[(size_t)r * HID + lane * 4];
        m.x = fmaxf(m.x, v.x);
        m.y = fmaxf(m.y, v.y);
        m.z = fmaxf(m.z, v.z);
        m.w = fmaxf(m.w, v.w);
    }
    *(float4*)&sm[warp][lane * 4] = m;
    __syncthreads();
    if (threadIdx.x < HID) {
        int f = threadIdx.x;
        float mm = sm[0][f];
#pragma unroll
        for (int w = 1; w < 8; w++) mm = fmaxf(mm, sm[w][f]);
        g_hg[g * HID + f] = mm;
    }
}

// ---------------- classifier head ----------------
__global__ void k_final(const float* __restrict__ Wc, const float* __restrict__ bc,
                        float* __restrict__ out, int nb) {
    int t = blockIdx.x * blockDim.x + threadIdx.x;
    if (t >= nb * 10) return;
    int g = t / 10;
    int c = t % 10;
    float acc = bc[c];
#pragma unroll 8
    for (int k = 0; k < HID; k++) acc += g_hg[g * HID + k] * Wc[k * 10 + c];
    out[t] = acc;
}

// ---------------- launch ----------------
extern "C" void kernel_launch(void* const* d_in, const int* in_sizes, int n_in,
                              void* d_out, int out_size) {
    const float* x   = (const float*)d_in[0];
    const float* W1  = (const float*)d_in[1];
    const float* b1  = (const float*)d_in[2];
    const float* W2  = (const float*)d_in[3];
    const float* b2  = (const float*)d_in[4];
    const float* Wc  = (const float*)d_in[5];
    const float* bc  = (const float*)d_in[6];
    const int*   src = (const int*)d_in[7];
    const int*   dst = (const int*)d_in[8];
    float* out = (float*)d_out;

    int e = in_sizes[7];
    int n = in_sizes[9];
    int nb_graphs = out_size / 10;
    int gsize = n / nb_graphs;
    int nbscan = (n + 1023) / 1024;
    int nGemm = (n + GBM - 1) / GBM;

    k_zero_deg<<<(n + 511) / 512, 512>>>(n);
    k_hist<<<(e + 511) / 512, 512>>>(dst, e);
    k_wprep<<<128, 256>>>(W1, W2);
    k_scanA<<<nbscan, 1024>>>(n);
    k_scanB<<<1, NB_SCAN>>>(nbscan);
    k_scanC<<<nbscan, 1024>>>(n, e);
    k_fill<<<(e + 511) / 512, 512>>>(src, dst, e);

    // layer 1
    k_spmm<<<(n + 7) / 8, 256>>>(0, x, n);
    k_gemm_tc<<<nGemm, 256>>>(0, x, b1, n);
    // layer 2
    k_spmm<<<(n + 7) / 8, 256>>>(1, x, n);
    k_gemm_tc<<<nGemm, 256>>>(1, x, b2, n);

    k_segmax<<<nb_graphs, 256>>>(gsize);
    k_final<<<1, 512>>>(Wc, bc, out, nb_graphs);
}

// round 10
// speedup vs baseline: 2.6111x; 1.0100x over previous
#include <cuda_runtime.h>
#include <cuda_bf16.h>
#include <cuda_fp16.h>
#include <cstdint>

#define N_NODES 100000
#define E_MAX   1600000
#define HID     128
#define NB_SCAN 128
#define GBM 128

typedef unsigned long long u64t;
typedef unsigned int u32t;

// ---------------- device scratch (no allocations allowed) ----------------
__device__ int   g_deg[N_NODES];
__device__ int   g_rowptr[N_NODES + 1];
__device__ int   g_fill[N_NODES];
__device__ int   g_bsum[NB_SCAN];
__device__ int   g_boff[NB_SCAN];
__device__ int   g_col[E_MAX];
__device__ float g_dinv[N_NODES];
__device__ float g_tx1[(size_t)N_NODES * HID];
__device__ float g_h1 [(size_t)N_NODES * HID];
__device__ float g_h2 [(size_t)N_NODES * HID];
__device__ float g_hg [64 * HID];
__device__ u32t  g_Wbhi[2 * HID * HID];
__device__ u32t  g_Wblo[2 * HID * HID];
__device__ u32t  g_fh [(size_t)N_NODES * (HID / 2)];   // fp16 dinv-premultiplied features

// ---------------- helpers ----------------
__device__ __forceinline__ u32t pack_bf16(float lo_val, float hi_val) {
    u32t r;
    asm("cvt.rn.bf16x2.f32 %0, %1, %2;" : "=r"(r) : "f"(hi_val), "f"(lo_val));
    return r;
}
__device__ __forceinline__ void mma_bf16(float* c, const u32t* a, const u32t* b) {
    asm volatile("mma.sync.aligned.m16n8k16.row.col.f32.bf16.bf16.f32 "
        "{%0,%1,%2,%3}, {%4,%5,%6,%7}, {%8,%9}, {%0,%1,%2,%3};"
        : "+f"(c[0]), "+f"(c[1]), "+f"(c[2]), "+f"(c[3])
        : "r"(a[0]), "r"(a[1]), "r"(a[2]), "r"(a[3]), "r"(b[0]), "r"(b[1]));
}

// ---------------- prep ----------------
__global__ void k_zero_deg(int n) {
    int i = blockIdx.x * blockDim.x + threadIdx.x;
    if (i < n) g_deg[i] = 0;
}

__global__ void k_hist(const int* __restrict__ dst, int e) {
    int i = blockIdx.x * blockDim.x + threadIdx.x;
    if (i < e) atomicAdd(&g_deg[dst[i]], 1);
}

__global__ void k_scanA(int n) {
    __shared__ int s[1024];
    int tid = threadIdx.x;
    int i = blockIdx.x * 1024 + tid;
    int v = (i < n) ? g_deg[i] : 0;
    s[tid] = v;
    __syncthreads();
    for (int off = 1; off < 1024; off <<= 1) {
        int t = (tid >= off) ? s[tid - off] : 0;
        __syncthreads();
        s[tid] += t;
        __syncthreads();
    }
    if (i < n) g_rowptr[i] = s[tid] - v;
    if (tid == 1023) g_bsum[blockIdx.x] = s[1023];
}

__global__ void k_scanB(int nb) {
    __shared__ int s[NB_SCAN];
    int tid = threadIdx.x;
    int v = (tid < nb) ? g_bsum[tid] : 0;
    s[tid] = v;
    __syncthreads();
    for (int off = 1; off < NB_SCAN; off <<= 1) {
        int t = (tid >= off) ? s[tid - off] : 0;
        __syncthreads();
        s[tid] += t;
        __syncthreads();
    }
    s[tid] -= v;
    g_boff[tid] = s[tid];
}

__global__ void k_scanC(int n, int e) {
    int i = blockIdx.x * 1024 + threadIdx.x;
    if (i < n) {
        int rp = g_rowptr[i] + g_boff[i >> 10];
        g_rowptr[i] = rp;
        g_fill[i]   = rp;
        g_dinv[i]   = rsqrtf(fmaxf((float)g_deg[i], 1.0f));
        if (i == n - 1) g_rowptr[n] = e;
    }
}

__global__ void k_fill(const int* __restrict__ src, const int* __restrict__ dst, int e) {
    int i = blockIdx.x * blockDim.x + threadIdx.x;
    if (i < e) {
        int p = atomicAdd(&g_fill[dst[i]], 1);
        g_col[p] = src[i];
    }
}

// ---------------- W prep (bf16 hi/lo, transposed, packed) ----------------
__global__ void k_wprep(const float* __restrict__ W1, const float* __restrict__ W2) {
    int i = blockIdx.x * 256 + threadIdx.x;
    int l  = i >> 14;
    int r  = i & 16383;
    int nn = r >> 7;
    int k2 = r & 127;
    const float* Wl = l ? W2 : W1;
    float v0 = Wl[(size_t)(2 * k2) * HID + nn];
    float v1 = Wl[(size_t)(2 * k2 + 1) * HID + nn];
    __nv_bfloat16 h0 = __float2bfloat16_rn(v0);
    __nv_bfloat16 h1 = __float2bfloat16_rn(v1);
    float l0 = v0 - __bfloat162float(h0);
    float l1 = v1 - __bfloat162float(h1);
    int o = l * (HID * HID) + nn * 128 + k2;
    g_Wbhi[o] = pack_bf16(__bfloat162float(h0), __bfloat162float(h1));
    g_Wblo[o] = pack_bf16(l0, l1);
}

// ---------------- feature -> fp16 (dinv-premultiplied) ----------------
__global__ void k_tohalf(int layer, const float* __restrict__ xin, int n) {
    const float* __restrict__ feat = (layer == 0) ? xin : g_h1;
    int idx = blockIdx.x * 256 + threadIdx.x;
    if (idx >= n * 32) return;
    int row = idx >> 5;
    int q   = idx & 31;
    float4 v = *(const float4*)&feat[(size_t)row * HID + q * 4];
    float w = g_dinv[row];
    __half2 a = __floats2half2_rn(v.x * w, v.y * w);
    __half2 b = __floats2half2_rn(v.z * w, v.w * w);
    uint2 o = make_uint2(*(u32t*)&a, *(u32t*)&b);
    *(uint2*)&g_fh[(size_t)row * (HID / 2) + q * 2] = o;
}

// ---------------- SpMM: fp16 gather, fp32 accumulate, x4 unroll dual acc ----------------
__global__ void k_spmm(int n) {
    int row = blockIdx.x * 8 + (threadIdx.x >> 5);
    if (row >= n) return;
    int lane = threadIdx.x & 31;
    int e0 = g_rowptr[row];
    int e1 = g_rowptr[row + 1];
    int co = lane * 2;   // u32 offset within row (covers cols lane*4 .. lane*4+3)
    float4 acc0 = make_float4(0.f, 0.f, 0.f, 0.f);
    float4 acc1 = make_float4(0.f, 0.f, 0.f, 0.f);
    int e = e0;
    for (; e + 4 <= e1; e += 4) {
        int s0 = g_col[e];
        int s1 = g_col[e + 1];
        int s2 = g_col[e + 2];
        int s3 = g_col[e + 3];
        uint2 f0 = *(const uint2*)&g_fh[(size_t)s0 * (HID / 2) + co];
        uint2 f1 = *(const uint2*)&g_fh[(size_t)s1 * (HID / 2) + co];
        uint2 f2 = *(const uint2*)&g_fh[(size_t)s2 * (HID / 2) + co];
        uint2 f3 = *(const uint2*)&g_fh[(size_t)s3 * (HID / 2) + co];
        float2 a0 = __half22float2(*(__half2*)&f0.x), b0 = __half22float2(*(__half2*)&f0.y);
        float2 a1 = __half22float2(*(__half2*)&f1.x), b1 = __half22float2(*(__half2*)&f1.y);
        float2 a2 = __half22float2(*(__half2*)&f2.x), b2 = __half22float2(*(__half2*)&f2.y);
        float2 a3 = __half22float2(*(__half2*)&f3.x), b3 = __half22float2(*(__half2*)&f3.y);
        acc0.x += a0.x; acc0.y += a0.y; acc0.z += b0.x; acc0.w += b0.y;
        acc1.x += a1.x; acc1.y += a1.y; acc1.z += b1.x; acc1.w += b1.y;
        acc0.x += a2.x; acc0.y += a2.y; acc0.z += b2.x; acc0.w += b2.y;
        acc1.x += a3.x; acc1.y += a3.y; acc1.z += b3.x; acc1.w += b3.y;
    }
    for (; e < e1; e++) {
        int s = g_col[e];
        uint2 f = *(const uint2*)&g_fh[(size_t)s * (HID / 2) + co];
        float2 a = __half22float2(*(__half2*)&f.x), b = __half22float2(*(__half2*)&f.y);
        acc0.x += a.x; acc0.y += a.y; acc0.z += b.x; acc0.w += b.y;
    }
    float sc = -g_dinv[row];
    float4 o;
    o.x = (acc0.x + acc1.x) * sc;
    o.y = (acc0.y + acc1.y) * sc;
    o.z = (acc0.z + acc1.z) * sc;
    o.w = (acc0.w + acc1.w) * sc;
    *(float4*)&g_tx1[(size_t)row * HID + lane * 4] = o;
}

// ---------------- tensor GEMM (round-7 proven): C = relu([Afeat|g_tx1]@W + b) ----------------
__global__ __launch_bounds__(256, 2) void k_gemm_tc(int layer,
                                                    const float* __restrict__ xin,
                                                    const float* __restrict__ bias,
                                                    int n) {
    const float* __restrict__ Afeat = (layer == 0) ? xin : g_h1;
    float* __restrict__ C = (layer == 0) ? g_h1 : g_h2;
    const u32t* __restrict__ Whi = &g_Wbhi[layer * (HID * HID)];
    const u32t* __restrict__ Wlo = &g_Wblo[layer * (HID * HID)];

    __shared__ u32t As_hi[2][GBM][8];
    __shared__ u32t As_lo[2][GBM][8];
    __shared__ u32t Ws_hi[2][HID][8];
    __shared__ u32t Ws_lo[2][HID][8];

    int tid  = threadIdx.x;
    int lane = tid & 31;
    int wid  = tid >> 5;
    int wm   = wid & 1;
    int wn   = wid >> 1;
    int lr   = lane >> 2;
    int lc   = lane & 3;
    int bm   = blockIdx.x * GBM;
    int swl  = lr & 6;
    int ca   = lc ^ swl;

    float acc[4][4][4];
#pragma unroll
    for (int mi = 0; mi < 4; mi++)
#pragma unroll
        for (int ni = 0; ni < 4; ni++)
#pragma unroll
            for (int q = 0; q < 4; q++) acc[mi][ni][q] = 0.f;

    int tr = tid >> 2;
    int tq = tid & 3;

    for (int kb = 0; kb < 8; kb++) {
        int kg = kb * 32;
        const float* __restrict__ A = (kg < HID) ? Afeat : g_tx1;
        int kcol = kg & (HID - 1);

#pragma unroll
        for (int h = 0; h < 2; h++) {
#pragma unroll
            for (int p = 0; p < 2; p++) {
                int rl = tr + p * 64;
                int sw = rl & 6;
                int cc = (tq * 2) ^ sw;
                int row = bm + rl;
                float4 v = make_float4(0.f, 0.f, 0.f, 0.f);
                if (row < n) v = *(const float4*)&A[(size_t)row * HID + kcol + h * 16 + tq * 4];
                __nv_bfloat16 bx = __float2bfloat16_rn(v.x);
                __nv_bfloat16 by = __float2bfloat16_rn(v.y);
                __nv_bfloat16 bz = __float2bfloat16_rn(v.z);
                __nv_bfloat16 bw = __float2bfloat16_rn(v.w);
                float fx = __bfloat162float(bx), fy = __bfloat162float(by);
                float fz = __bfloat162float(bz), fw = __bfloat162float(bw);
                uint2 hi = make_uint2(pack_bf16(fx, fy), pack_bf16(fz, fw));
                uint2 lo = make_uint2(pack_bf16(v.x - fx, v.y - fy),
                                      pack_bf16(v.z - fz, v.w - fw));
                *(uint2*)&As_hi[h][rl][cc] = hi;
                *(uint2*)&As_lo[h][rl][cc] = lo;
                int wo = rl * 128 + (kg + h * 16) / 2 + tq * 2;
                *(uint2*)&Ws_hi[h][rl][cc] = *(const uint2*)&Whi[wo];
                *(uint2*)&Ws_lo[h][rl][cc] = *(const uint2*)&Wlo[wo];
            }
        }
        __syncthreads();

#pragma unroll
        for (int h = 0; h < 2; h++) {
            u32t bh[4][2], bl[4][2];
#pragma unroll
            for (int ni = 0; ni < 4; ni++) {
                int n0 = wn * 32 + ni * 8 + lr;
                bh[ni][0] = Ws_hi[h][n0][ca];
                bh[ni][1] = Ws_hi[h][n0][ca ^ 4];
                bl[ni][0] = Ws_lo[h][n0][ca];
                bl[ni][1] = Ws_lo[h][n0][ca ^ 4];
            }
#pragma unroll
            for (int mi = 0; mi < 4; mi++) {
                int m0 = wm * 64 + mi * 16;
                u32t ah[4], al[4];
                ah[0] = As_hi[h][m0 + lr][ca];
                ah[1] = As_hi[h][m0 + lr + 8][ca];
                ah[2] = As_hi[h][m0 + lr][ca ^ 4];
                ah[3] = As_hi[h][m0 + lr + 8][ca ^ 4];
                al[0] = As_lo[h][m0 + lr][ca];
                al[1] = As_lo[h][m0 + lr + 8][ca];
                al[2] = As_lo[h][m0 + lr][ca ^ 4];
                al[3] = As_lo[h][m0 + lr + 8][ca ^ 4];
#pragma unroll
                for (int ni = 0; ni < 4; ni++) {
                    mma_bf16(acc[mi][ni], ah, bh[ni]);
                    mma_bf16(acc[mi][ni], ah, bl[ni]);
                    mma_bf16(acc[mi][ni], al, bh[ni]);
                }
            }
        }
        __syncthreads();
    }

#pragma unroll
    for (int mi = 0; mi < 4; mi++) {
        int r0 = bm + wm * 64 + mi * 16 + lr;
        int r1 = r0 + 8;
#pragma unroll
        for (int ni = 0; ni < 4; ni++) {
            int col = wn * 32 + ni * 8 + lc * 2;
            float2 bv = *(const float2*)&bias[col];
            if (r0 < n) {
                float2 o;
                o.x = fmaxf(acc[mi][ni][0] + bv.x, 0.f);
                o.y = fmaxf(acc[mi][ni][1] + bv.y, 0.f);
                *(float2*)&C[(size_t)r0 * HID + col] = o;
            }
            if (r1 < n) {
                float2 o;
                o.x = fmaxf(acc[mi][ni][2] + bv.x, 0.f);
                o.y = fmaxf(acc[mi][ni][3] + bv.y, 0.f);
                *(float2*)&C[(size_t)r1 * HID + col] = o;
            }
        }
    }
}

// ---------------- segment max ----------------
__global__ void k_segmax(int gsize) {
    __shared__ float sm[8][HID];
    int g = blockIdx.x;
    int warp = threadIdx.x >> 5;
    int lane = threadIdx.x & 31;
    float4 m = make_float4(0.f, 0.f, 0.f, 0.f);
    int r0 = g * gsize;
    for (int r = r0 + warp; r < r0 + gsize; r += 8) {
        float4 v = *(const float4*)&g_h2[(size_t)r * HID + lane * 4];
        m.x = fmaxf(m.x, v.x);
        m.y = fmaxf(m.y, v.y);
        m.z = fmaxf(m.z, v.z);
        m.w = fmaxf(m.w, v.w);
    }
    *(float4*)&sm[warp][lane * 4] = m;
    __syncthreads();
    if (threadIdx.x < HID) {
        int f = threadIdx.x;
        float mm = sm[0][f];
#pragma unroll
        for (int w = 1; w < 8; w++) mm = fmaxf(mm, sm[w][f]);
        g_hg[g * HID + f] = mm;
    }
}

// ---------------- classifier head ----------------
__global__ void k_final(const float* __restrict__ Wc, const float* __restrict__ bc,
                        float* __restrict__ out, int nb) {
    int t = blockIdx.x * blockDim.x + threadIdx.x;
    if (t >= nb * 10) return;
    int g = t / 10;
    int c = t % 10;
    float acc = bc[c];
#pragma unroll 8
    for (int k = 0; k < HID; k++) acc += g_hg[g * HID + k] * Wc[k * 10 + c];
    out[t] = acc;
}

// ---------------- launch ----------------
extern "C" void kernel_launch(void* const* d_in, const int* in_sizes, int n_in,
                              void* d_out, int out_size) {
    const float* x   = (const float*)d_in[0];
    const float* W1  = (const float*)d_in[1];
    const float* b1  = (const float*)d_in[2];
    const float* W2  = (const float*)d_in[3];
    const float* b2  = (const float*)d_in[4];
    const float* Wc  = (const float*)d_in[5];
    const float* bc  = (const float*)d_in[6];
    const int*   src = (const int*)d_in[7];
    const int*   dst = (const int*)d_in[8];
    float* out = (float*)d_out;

    int e = in_sizes[7];
    int n = in_sizes[9];
    int nb_graphs = out_size / 10;
    int gsize = n / nb_graphs;
    int nbscan = (n + 1023) / 1024;
    int nGemm = (n + GBM - 1) / GBM;
    int nConv = (n * 32 + 255) / 256;

    k_zero_deg<<<(n + 511) / 512, 512>>>(n);
    k_hist<<<(e + 511) / 512, 512>>>(dst, e);
    k_wprep<<<128, 256>>>(W1, W2);
    k_scanA<<<nbscan, 1024>>>(n);
    k_scanB<<<1, NB_SCAN>>>(nbscan);
    k_scanC<<<nbscan, 1024>>>(n, e);
    k_fill<<<(e + 511) / 512, 512>>>(src, dst, e);

    // layer 1
    k_tohalf<<<nConv, 256>>>(0, x, n);
    k_spmm<<<(n + 7) / 8, 256>>>(n);
    k_gemm_tc<<<nGemm, 256>>>(0, x, b1, n);
    // layer 2
    k_tohalf<<<nConv, 256>>>(1, x, n);
    k_spmm<<<(n + 7) / 8, 256>>>(n);
    k_gemm_tc<<<nGemm, 256>>>(1, x, b2, n);

    k_segmax<<<nb_graphs, 256>>>(gsize);
    k_final<<<1, 512>>>(Wc, bc, out, nb_graphs);
}